// round 15
// baseline (speedup 1.0000x reference)
#include <cuda_runtime.h>
#include <cuda_bf16.h>
#include <cstdint>
#include <cstddef>

#define SEQLEN 512
#define BATCH  64
#define HID    512
#define INP    512
#define G4     2048
#define NB_REC 128
#define MTOT   (SEQLEN * BATCH)

// ---------------- device scratch ----------------
__device__ float g_xproj[(size_t)SEQLEN * BATCH * G4];
__device__ int   g_flags[4][32];          // [bi][0..1] = per-(bi,half) publish counters
__device__ __align__(256) __nv_bfloat16 g_Ah[(size_t)MTOT * INP];
__device__ __align__(256) __nv_bfloat16 g_Al[(size_t)MTOT * INP];
__device__ __align__(256) __nv_bfloat16 g_Wh[(size_t)G4 * INP];
__device__ __align__(256) __nv_bfloat16 g_Wl[(size_t)G4 * INP];
__device__ __align__(256) __nv_bfloat16 g_Rh[(size_t)G4 * HID];
__device__ __align__(256) __nv_bfloat16 g_Rl[(size_t)G4 * HID];
// h exchange: [buf][bi][plane][16 kt-slabs x 16 b x 80B] bf16 pair-packed words
__device__ __align__(256) unsigned g_hbf[2][4][2][5120];

// ---------------- helpers ----------------
__device__ __forceinline__ float sigf(float x) { return 1.0f / (1.0f + __expf(-x)); }
__device__ __forceinline__ float tanhf_acc(float x) {
    return 2.0f / (1.0f + __expf(-2.0f * x)) - 1.0f;
}
__device__ __forceinline__ unsigned smem_u32(const void* p) {
    unsigned a;
    asm("{ .reg .u64 t; cvta.to.shared.u64 t, %1; cvt.u32.u64 %0, t; }" : "=r"(a) : "l"(p));
    return a;
}
__device__ __forceinline__ void cp16(unsigned dst, const void* src) {
    asm volatile("cp.async.cg.shared.global [%0], [%1], 16;" :: "r"(dst), "l"(src));
}
__device__ __forceinline__ void ldsm4(unsigned* r, unsigned addr) {
    asm volatile("ldmatrix.sync.aligned.m8n8.x4.shared.b16 {%0,%1,%2,%3}, [%4];"
                 : "=r"(r[0]), "=r"(r[1]), "=r"(r[2]), "=r"(r[3]) : "r"(addr));
}
__device__ __forceinline__ void mma_bf16(float* d, const unsigned* a, const unsigned* b) {
    asm("mma.sync.aligned.m16n8k16.row.col.f32.bf16.bf16.f32 "
        "{%0,%1,%2,%3}, {%4,%5,%6,%7}, {%8,%9}, {%0,%1,%2,%3};"
        : "+f"(d[0]), "+f"(d[1]), "+f"(d[2]), "+f"(d[3])
        : "r"(a[0]), "r"(a[1]), "r"(a[2]), "r"(a[3]), "r"(b[0]), "r"(b[1]));
}
__device__ __forceinline__ int ld_acq(const int* p) {
    int v;
    asm volatile("ld.acquire.gpu.global.s32 %0, [%1];" : "=r"(v) : "l"(p) : "memory");
    return v;
}
__device__ __forceinline__ void red_rel_add(int* p, int v) {
    asm volatile("red.release.gpu.global.add.s32 [%0], %1;" :: "l"(p), "r"(v) : "memory");
}

// =====================================================================================
// fp32 -> bf16 hi/lo split. Block 0 also zeroes recurrence counters.
// =====================================================================================
__global__ void conv_split(const float* __restrict__ src, __nv_bfloat16* __restrict__ hi,
                           __nv_bfloat16* __restrict__ lo, int n4)
{
    if (blockIdx.x == 0 && threadIdx.x < 128) ((int*)g_flags)[threadIdx.x] = 0;
    int i = blockIdx.x * blockDim.x + threadIdx.x;
    int stride = gridDim.x * blockDim.x;
    for (; i < n4; i += stride) {
        float4 v = ((const float4*)src)[i];
        float f[4] = {v.x, v.y, v.z, v.w};
        unsigned hv0 = 0, hv1 = 0, lv0 = 0, lv1 = 0;
        #pragma unroll
        for (int j = 0; j < 4; j++) {
            __nv_bfloat16 h = __float2bfloat16(f[j]);
            __nv_bfloat16 l = __float2bfloat16(f[j] - __bfloat162float(h));
            unsigned hb = (unsigned)__bfloat16_as_ushort(h);
            unsigned lb = (unsigned)__bfloat16_as_ushort(l);
            if (j < 2) { hv0 |= hb << (16 * j);       lv0 |= lb << (16 * j); }
            else       { hv1 |= hb << (16 * (j - 2)); lv1 |= lb << (16 * (j - 2)); }
        }
        uint2 hh; hh.x = hv0; hh.y = hv1;
        uint2 ll; ll.x = lv0; ll.y = lv1;
        ((uint2*)hi)[i] = hh;
        ((uint2*)lo)[i] = ll;
    }
}

// =====================================================================================
// Kernel 1: xproj GEMM — EXACT round-13/14 version (128x128 tile, 2-stage, ldmatrix)
// =====================================================================================
#define KT 32
#define APLANE 10240
#define BPLANE 10240
#define STG_SZ (2 * APLANE + 2 * BPLANE)    // 40960
#define GEMM_SMEM (2 * STG_SZ)              // 81920

__global__ __launch_bounds__(256, 2)
void gemm_hmma(const float* __restrict__ bih, const float* __restrict__ bhh)
{
    extern __shared__ char smraw[];
    const unsigned SB = smem_u32(smraw);
    const int tid  = threadIdx.x;
    const int lane = tid & 31;
    const int wid  = tid >> 5;
    const int wm   = wid >> 1;
    const int wn   = wid & 1;
    const int g    = lane >> 2;
    const int t    = lane & 3;
    const int n0   = blockIdx.x * 128;
    const int m0   = blockIdx.y * 128;

    const unsigned rA = (unsigned)(lane & 15);
    const unsigned kA = (unsigned)((lane >> 4) * 16);
    const unsigned rB = (unsigned)(((lane >> 4) << 3) | (lane & 7));
    const unsigned kB = (unsigned)(((lane >> 3) & 1) * 16);

    auto copy_tile = [&](int kt, int sel) {
        const unsigned sb = SB + (unsigned)sel * STG_SZ;
        const int k0 = kt * KT;
        #pragma unroll
        for (int u = 0; u < 4; u++) {
            int idx = tid + u * 256;
            int plane = idx >> 9, r = (idx >> 2) & 127, ch = idx & 3;
            const __nv_bfloat16* src = (plane ? g_Al : g_Ah)
                                     + (size_t)(m0 + r) * INP + k0 + ch * 8;
            cp16(sb + (unsigned)(plane * APLANE + r * 80 + ch * 16), src);
        }
        #pragma unroll
        for (int u = 0; u < 4; u++) {
            int idx = tid + u * 256;
            int plane = idx >> 9, r = (idx >> 2) & 127, ch = idx & 3;
            const __nv_bfloat16* src = (plane ? g_Wl : g_Wh)
                                     + (size_t)(n0 + r) * INP + k0 + ch * 8;
            cp16(sb + (unsigned)(2 * APLANE + plane * BPLANE + r * 80 + ch * 16), src);
        }
        asm volatile("cp.async.commit_group;");
    };

    float d[2][8][4];
    #pragma unroll
    for (int i = 0; i < 2; i++)
        #pragma unroll
        for (int j = 0; j < 8; j++)
            #pragma unroll
            for (int q = 0; q < 4; q++) d[i][j][q] = 0.f;

    copy_tile(0, 0);
    copy_tile(1, 1);

    for (int kt = 0; kt < 16; kt++) {
        if (kt < 15) asm volatile("cp.async.wait_group 1;" ::: "memory");
        else         asm volatile("cp.async.wait_group 0;" ::: "memory");
        __syncthreads();

        const unsigned sb = SB + (unsigned)(kt & 1) * STG_SZ;
        #pragma unroll
        for (int sub = 0; sub < 2; sub++) {
            const unsigned ko = (unsigned)(sub * 32);
            unsigned ah[2][4], al[2][4];
            #pragma unroll
            for (int i = 0; i < 2; i++) {
                unsigned ra = sb + (unsigned)((wm * 32 + i * 16 + rA) * 80) + ko + kA;
                ldsm4(ah[i], ra);
                ldsm4(al[i], ra + APLANE);
            }
            #pragma unroll
            for (int jp = 0; jp < 4; jp++) {
                unsigned bh4[4], bl4[4];
                unsigned rb = sb + 2 * APLANE
                            + (unsigned)((wn * 64 + jp * 16 + rB) * 80) + ko + kB;
                ldsm4(bh4, rb);
                ldsm4(bl4, rb + BPLANE);
                #pragma unroll
                for (int i = 0; i < 2; i++)
                    #pragma unroll
                    for (int jj = 0; jj < 2; jj++) {
                        float* dd = d[i][jp * 2 + jj];
                        mma_bf16(dd, ah[i], &bh4[jj * 2]);
                        mma_bf16(dd, ah[i], &bl4[jj * 2]);
                        mma_bf16(dd, al[i], &bh4[jj * 2]);
                    }
            }
        }
        __syncthreads();
        if (kt + 2 < 16) copy_tile(kt + 2, kt & 1);
    }

    #pragma unroll
    for (int j = 0; j < 8; j++) {
        int col = n0 + wn * 64 + j * 8 + t * 2;
        float b0 = bih[col] + bhh[col];
        float b1 = bih[col + 1] + bhh[col + 1];
        #pragma unroll
        for (int i = 0; i < 2; i++) {
            int row = m0 + wm * 32 + i * 16 + g;
            float2 v0; v0.x = d[i][j][0] + b0; v0.y = d[i][j][1] + b1;
            float2 v1; v1.x = d[i][j][2] + b0; v1.y = d[i][j][3] + b1;
            *(float2*)&g_xproj[(size_t)row * G4 + col] = v0;
            *(float2*)&g_xproj[(size_t)(row + 8) * G4 + col] = v1;
        }
    }
}

// =====================================================================================
// Kernel 2: persistent recurrence — per-(bi,half) counters, per-warp release publish,
// red-read/compute split so block syncs sit off the publish path.
// Half 0 (warps 0-7) consumes kt slabs 0-7 <- producers cj 0-15 -> cnt[bi][0].
// Half 1 (warps 8-15) consumes slabs 8-15 <- producers cj 16-31 -> cnt[bi][1].
// =====================================================================================
#define SM_WH  0u
#define SM_WL  81920u
#define SM_HH  163840u
#define SM_HL  184320u
#define SM_RED 204800u
#define REC_SMEM (204800 + 4 * 1088 * 4)    // 222208

__global__ __launch_bounds__(512, 1)
void lstm_rec(const float* __restrict__ h0, const float* __restrict__ c0,
              float* __restrict__ out, int write_hc)
{
    extern __shared__ char sm[];
    const unsigned SB = smem_u32(sm);
    float* red = (float*)(sm + SM_RED);

    const int tid  = threadIdx.x;
    const int bi   = blockIdx.x >> 5;
    const int cj   = blockIdx.x & 31;
    const int lane = tid & 31;
    const int wid  = tid >> 5;
    const int nh   = wid & 3;
    const int kq   = wid >> 2;
    const int half = tid >> 8;              // consumer half
    const int cjhalf = cj >> 4;             // producer half

    const unsigned rA = (unsigned)(lane & 15);
    const unsigned kA = (unsigned)((lane >> 4) * 16);
    const unsigned rB = (unsigned)(((lane >> 4) << 3) | (lane & 7));
    const unsigned kB = (unsigned)(((lane >> 3) & 1) * 16);

    const int cb   = (tid & 255) >> 4;
    const int cjl  = tid & 15;
    const size_t hofs = (size_t)(bi * 16 + cb) * HID + cj * 16 + cjl;
    const int pp    = cj * 8 + (cjl >> 1);
    const int wslot = (pp >> 4) * 320 + cb * 20 + (pp & 15);

    int* cnt0 = &g_flags[bi][0];
    int* cnt1 = &g_flags[bi][1];
    int* cntp = &g_flags[bi][cjhalf];

    // ---- resident W_hh hi/lo ----
    for (int idx = tid; idx < 8192; idx += 512) {
        int plane = idx >> 12;
        int q = idx & 4095;
        int r = q >> 6, kt = (q >> 2) & 15, ch = q & 3;
        int ty = r >> 4, j = r & 15;
        const __nv_bfloat16* base = plane ? g_Rl : g_Rh;
        const __nv_bfloat16* src =
            base + (size_t)(ty * HID + cj * 16 + j) * HID + kt * 32 + ch * 8;
        cp16(SB + (plane ? SM_WL : SM_WH)
                + (unsigned)(kt * 5120 + r * 80 + ch * 16), src);
    }
    asm volatile("cp.async.commit_group;");

    // ---- init-publish h0 slice (per-warp release) ----
    if (tid < 256) {
        float hv = h0[hofs];
        __nv_bfloat16 hb = __float2bfloat16(hv);
        unsigned hu = (unsigned)__bfloat16_as_ushort(hb);
        unsigned lu = (unsigned)__bfloat16_as_ushort(
                          __float2bfloat16(hv - __bfloat162float(hb)));
        unsigned hn2 = __shfl_down_sync(0xffffffffu, hu, 1);
        unsigned ln2 = __shfl_down_sync(0xffffffffu, lu, 1);
        if (!(cjl & 1)) {
            g_hbf[0][bi][0][wslot] = hu | (hn2 << 16);
            g_hbf[0][bi][1][wslot] = lu | (ln2 << 16);
        }
        __syncwarp();
        if (lane == 0) red_rel_add(cntp, 1);
    }

    asm volatile("cp.async.wait_group 0;" ::: "memory");
    float creg = (tid < 256) ? c0[hofs] : 0.0f;
    __syncthreads();

    for (int t = 0; t < SEQLEN; t++) {
        // ---- prefetch x_proj gates (before any wait) ----
        float xg0 = 0.f, xg1 = 0.f, xg2 = 0.f, xg3 = 0.f;
        if (tid < 256) {
            size_t xofs = ((size_t)t * BATCH + bi * 16 + cb) * G4 + cj * 16 + cjl;
            xg0 = __ldcg(&g_xproj[xofs]);
            xg1 = __ldcg(&g_xproj[xofs + HID]);
            xg2 = __ldcg(&g_xproj[xofs + 2 * HID]);
            xg3 = __ldcg(&g_xproj[xofs + 3 * HID]);
        }

        // ---- per-half wait: only this half's 16 producers (128 warp-arrivals) ----
        const int target = 128 * (t + 1);
        if (tid == 0)   { while (ld_acq(cnt0) < target) { } }
        if (tid == 256) { while (ld_acq(cnt1) < target) { } }
        if (half == 0) asm volatile("bar.sync 1, 256;" ::: "memory");
        else           asm volatile("bar.sync 2, 256;" ::: "memory");

        // ---- stage this half's kt slabs (20 KB) ----
        {
            const char* hsrc = (const char*)&g_hbf[t & 1][bi][0][0];
            const int tl = tid & 255;
            const unsigned hbase = (unsigned)(half * 10240);
            #pragma unroll
            for (int u = 0; u < 5; u++) {
                int idx = tl + u * 256;          // 0..1279
                int plane = idx >= 640;
                unsigned off = hbase + (unsigned)((idx - plane * 640) * 16);
                cp16(SB + (plane ? SM_HL : SM_HH) + off,
                     hsrc + plane * 20480 + off);
            }
            asm volatile("cp.async.commit_group;");
            asm volatile("cp.async.wait_group 0;" ::: "memory");
            if (half == 0) asm volatile("bar.sync 1, 256;" ::: "memory");
            else           asm volatile("bar.sync 2, 256;" ::: "memory");
        }

        // ---- HMMA: warp (nh, kq): 8 k16 chunks x 2 B-tiles x 3 split terms ----
        float d0[2][4] = {{0,0,0,0},{0,0,0,0}};
        float d1[2][4] = {{0,0,0,0},{0,0,0,0}};
        float d2[2][4] = {{0,0,0,0},{0,0,0,0}};
        #pragma unroll
        for (int c = 0; c < 8; c++) {
            int k16 = kq * 8 + c;
            unsigned hOff = (unsigned)((k16 >> 1) * 1280 + (k16 & 1) * 32);
            unsigned wOff = (unsigned)((k16 >> 1) * 5120 + (k16 & 1) * 32);
            unsigned ah4[4], al4[4], wh4[4], wl4[4];
            ldsm4(ah4, SB + SM_HH + hOff + rA * 80 + kA);
            ldsm4(al4, SB + SM_HL + hOff + rA * 80 + kA);
            ldsm4(wh4, SB + SM_WH + wOff + (unsigned)((nh * 16 + rB) * 80) + kB);
            ldsm4(wl4, SB + SM_WL + wOff + (unsigned)((nh * 16 + rB) * 80) + kB);
            #pragma unroll
            for (int jt = 0; jt < 2; jt++) {
                mma_bf16(d0[jt], ah4, &wh4[jt * 2]);
                mma_bf16(d1[jt], ah4, &wl4[jt * 2]);
                mma_bf16(d2[jt], al4, &wh4[jt * 2]);
            }
        }
        {
            const int g = lane >> 2, tq = lane & 3;
            #pragma unroll
            for (int jt = 0; jt < 2; jt++) {
                int n = nh * 16 + jt * 8 + tq * 2;
                int base = kq * 1088 + n * 17;
                red[base + g]          = d0[jt][0] + d1[jt][0] + d2[jt][0];
                red[base + 17 + g]     = d0[jt][1] + d1[jt][1] + d2[jt][1];
                red[base + g + 8]      = d0[jt][2] + d1[jt][2] + d2[jt][2];
                red[base + 17 + g + 8] = d0[jt][3] + d1[jt][3] + d2[jt][3];
            }
        }
        __syncthreads();      // all red partials visible

        // ---- phase C part 1: red reads only ----
        float s[4] = {0.f, 0.f, 0.f, 0.f};
        if (tid < 256) {
            #pragma unroll
            for (int ty = 0; ty < 4; ty++) {
                int n = ty * 16 + cjl;
                float v = red[n * 17 + cb];
                #pragma unroll
                for (int kk = 1; kk < 4; kk++)
                    v += red[kk * 1088 + n * 17 + cb];
                s[ty] = v;
            }
        }
        __syncthreads();      // red free for next step's MMA (both halves)

        // ---- phase C part 2: gates + per-warp publish (off block-sync path) ----
        float hn = 0.f;
        if (tid < 256) {
            float iv = sigf(s[0] + xg0);
            float fv = sigf(s[1] + xg1);
            float gv = tanhf_acc(s[2] + xg2);
            float ov = sigf(s[3] + xg3);
            creg = fv * creg + iv * gv;
            hn = ov * tanhf_acc(creg);

            __nv_bfloat16 hb = __float2bfloat16(hn);
            unsigned hu = (unsigned)__bfloat16_as_ushort(hb);
            unsigned lu = (unsigned)__bfloat16_as_ushort(
                              __float2bfloat16(hn - __bfloat162float(hb)));
            unsigned hn2 = __shfl_down_sync(0xffffffffu, hu, 1);
            unsigned ln2 = __shfl_down_sync(0xffffffffu, lu, 1);
            if (!(cjl & 1)) {
                g_hbf[(t + 1) & 1][bi][0][wslot] = hu | (hn2 << 16);
                g_hbf[(t + 1) & 1][bi][1][wslot] = lu | (ln2 << 16);
            }
            __syncwarp();
            if (lane == 0) red_rel_add(cntp, 1);

            // ---- out stores off the publish path ----
            out[(size_t)t * (BATCH * HID) + hofs] = hn;
            if (write_hc && t == SEQLEN - 1) {
                out[(size_t)SEQLEN * BATCH * HID + hofs] = hn;
                out[(size_t)SEQLEN * BATCH * HID + BATCH * HID + hofs] = creg;
            }
        }
    }
}

// =====================================================================================
extern "C" void kernel_launch(void* const* d_in, const int* in_sizes, int n_in,
                              void* d_out, int out_size)
{
    const float* input = (const float*)d_in[0];
    const float* h0    = (const float*)d_in[1];
    const float* c0    = (const float*)d_in[2];
    const float* Wih   = (const float*)d_in[3];
    const float* Whh   = (const float*)d_in[4];
    const float* bih   = (const float*)d_in[5];
    const float* bhh   = (const float*)d_in[6];
    (void)in_sizes; (void)n_in;

    float* out = (float*)d_out;
    const int n_outputs = SEQLEN * BATCH * HID;
    int write_hc = (out_size >= n_outputs + 2 * BATCH * HID) ? 1 : 0;

    static int configured = 0;
    if (!configured) {
        cudaFuncSetAttribute(gemm_hmma, cudaFuncAttributeMaxDynamicSharedMemorySize,
                             GEMM_SMEM);
        cudaFuncSetAttribute(lstm_rec, cudaFuncAttributeMaxDynamicSharedMemorySize,
                             REC_SMEM);
        configured = 1;
    }

    __nv_bfloat16 *ah, *al, *wh, *wl, *rh, *rl;
    cudaGetSymbolAddress((void**)&ah, g_Ah);
    cudaGetSymbolAddress((void**)&al, g_Al);
    cudaGetSymbolAddress((void**)&wh, g_Wh);
    cudaGetSymbolAddress((void**)&wl, g_Wl);
    cudaGetSymbolAddress((void**)&rh, g_Rh);
    cudaGetSymbolAddress((void**)&rl, g_Rl);

    conv_split<<<512, 256>>>(Wih, wh, wl, (G4 * INP) / 4);
    conv_split<<<512, 256>>>(Whh, rh, rl, (G4 * HID) / 4);
    conv_split<<<2048, 256>>>(input, ah, al, (MTOT * INP) / 4);
    gemm_hmma<<<dim3(G4 / 128, MTOT / 128), 256, GEMM_SMEM>>>(bih, bhh);
    lstm_rec<<<NB_REC, 512, REC_SMEM>>>(h0, c0, out, write_hc);
}

// round 16
// speedup vs baseline: 1.0625x; 1.0625x over previous
#include <cuda_runtime.h>
#include <cuda_bf16.h>
#include <cstdint>
#include <cstddef>

#define SEQLEN 512
#define BATCH  64
#define HID    512
#define INP    512
#define G4     2048
#define NB_REC 128
#define MTOT   (SEQLEN * BATCH)

// ---------------- device scratch ----------------
__device__ float g_xproj[(size_t)SEQLEN * BATCH * G4];
__device__ int   g_flags[4][32];          // [0][0..3] = per-bi publish counters
__device__ __align__(256) __nv_bfloat16 g_Ah[(size_t)MTOT * INP];
__device__ __align__(256) __nv_bfloat16 g_Al[(size_t)MTOT * INP];
__device__ __align__(256) __nv_bfloat16 g_Wh[(size_t)G4 * INP];
__device__ __align__(256) __nv_bfloat16 g_Wl[(size_t)G4 * INP];
__device__ __align__(256) __nv_bfloat16 g_Rh[(size_t)G4 * HID];
__device__ __align__(256) __nv_bfloat16 g_Rl[(size_t)G4 * HID];
// h exchange: [buf][bi][plane][16 kt-slabs x 16 b x 80B] bf16 pair-packed words
__device__ __align__(256) unsigned g_hbf[2][4][2][5120];

// ---------------- helpers ----------------
__device__ __forceinline__ float sigf(float x) { return 1.0f / (1.0f + __expf(-x)); }
__device__ __forceinline__ float tanhf_acc(float x) {
    return 2.0f / (1.0f + __expf(-2.0f * x)) - 1.0f;
}
__device__ __forceinline__ unsigned smem_u32(const void* p) {
    unsigned a;
    asm("{ .reg .u64 t; cvta.to.shared.u64 t, %1; cvt.u32.u64 %0, t; }" : "=r"(a) : "l"(p));
    return a;
}
__device__ __forceinline__ void cp16(unsigned dst, const void* src) {
    asm volatile("cp.async.cg.shared.global [%0], [%1], 16;" :: "r"(dst), "l"(src));
}
__device__ __forceinline__ void ldsm4(unsigned* r, unsigned addr) {
    asm volatile("ldmatrix.sync.aligned.m8n8.x4.shared.b16 {%0,%1,%2,%3}, [%4];"
                 : "=r"(r[0]), "=r"(r[1]), "=r"(r[2]), "=r"(r[3]) : "r"(addr));
}
__device__ __forceinline__ void mma_bf16(float* d, const unsigned* a, const unsigned* b) {
    asm("mma.sync.aligned.m16n8k16.row.col.f32.bf16.bf16.f32 "
        "{%0,%1,%2,%3}, {%4,%5,%6,%7}, {%8,%9}, {%0,%1,%2,%3};"
        : "+f"(d[0]), "+f"(d[1]), "+f"(d[2]), "+f"(d[3])
        : "r"(a[0]), "r"(a[1]), "r"(a[2]), "r"(a[3]), "r"(b[0]), "r"(b[1]));
}
__device__ __forceinline__ int ld_acq(const int* p) {
    int v;
    asm volatile("ld.acquire.gpu.global.s32 %0, [%1];" : "=r"(v) : "l"(p) : "memory");
    return v;
}
__device__ __forceinline__ void red_rel_add(int* p, int v) {
    asm volatile("red.release.gpu.global.add.s32 [%0], %1;" :: "l"(p), "r"(v) : "memory");
}

// =====================================================================================
// fp32 -> bf16 hi/lo split. Block 0 also zeroes recurrence counters.
// =====================================================================================
__global__ void conv_split(const float* __restrict__ src, __nv_bfloat16* __restrict__ hi,
                           __nv_bfloat16* __restrict__ lo, int n4)
{
    if (blockIdx.x == 0 && threadIdx.x < 128) ((int*)g_flags)[threadIdx.x] = 0;
    int i = blockIdx.x * blockDim.x + threadIdx.x;
    int stride = gridDim.x * blockDim.x;
    for (; i < n4; i += stride) {
        float4 v = ((const float4*)src)[i];
        float f[4] = {v.x, v.y, v.z, v.w};
        unsigned hv0 = 0, hv1 = 0, lv0 = 0, lv1 = 0;
        #pragma unroll
        for (int j = 0; j < 4; j++) {
            __nv_bfloat16 h = __float2bfloat16(f[j]);
            __nv_bfloat16 l = __float2bfloat16(f[j] - __bfloat162float(h));
            unsigned hb = (unsigned)__bfloat16_as_ushort(h);
            unsigned lb = (unsigned)__bfloat16_as_ushort(l);
            if (j < 2) { hv0 |= hb << (16 * j);       lv0 |= lb << (16 * j); }
            else       { hv1 |= hb << (16 * (j - 2)); lv1 |= lb << (16 * (j - 2)); }
        }
        uint2 hh; hh.x = hv0; hh.y = hv1;
        uint2 ll; ll.x = lv0; ll.y = lv1;
        ((uint2*)hi)[i] = hh;
        ((uint2*)lo)[i] = ll;
    }
}

// =====================================================================================
// Kernel 1: xproj GEMM — EXACT round-13/14 version (128x128 tile, 2-stage, ldmatrix)
// =====================================================================================
#define KT 32
#define APLANE 10240
#define BPLANE 10240
#define STG_SZ (2 * APLANE + 2 * BPLANE)    // 40960
#define GEMM_SMEM (2 * STG_SZ)              // 81920

__global__ __launch_bounds__(256, 2)
void gemm_hmma(const float* __restrict__ bih, const float* __restrict__ bhh)
{
    extern __shared__ char smraw[];
    const unsigned SB = smem_u32(smraw);
    const int tid  = threadIdx.x;
    const int lane = tid & 31;
    const int wid  = tid >> 5;
    const int wm   = wid >> 1;
    const int wn   = wid & 1;
    const int g    = lane >> 2;
    const int t    = lane & 3;
    const int n0   = blockIdx.x * 128;
    const int m0   = blockIdx.y * 128;

    const unsigned rA = (unsigned)(lane & 15);
    const unsigned kA = (unsigned)((lane >> 4) * 16);
    const unsigned rB = (unsigned)(((lane >> 4) << 3) | (lane & 7));
    const unsigned kB = (unsigned)(((lane >> 3) & 1) * 16);

    auto copy_tile = [&](int kt, int sel) {
        const unsigned sb = SB + (unsigned)sel * STG_SZ;
        const int k0 = kt * KT;
        #pragma unroll
        for (int u = 0; u < 4; u++) {
            int idx = tid + u * 256;
            int plane = idx >> 9, r = (idx >> 2) & 127, ch = idx & 3;
            const __nv_bfloat16* src = (plane ? g_Al : g_Ah)
                                     + (size_t)(m0 + r) * INP + k0 + ch * 8;
            cp16(sb + (unsigned)(plane * APLANE + r * 80 + ch * 16), src);
        }
        #pragma unroll
        for (int u = 0; u < 4; u++) {
            int idx = tid + u * 256;
            int plane = idx >> 9, r = (idx >> 2) & 127, ch = idx & 3;
            const __nv_bfloat16* src = (plane ? g_Wl : g_Wh)
                                     + (size_t)(n0 + r) * INP + k0 + ch * 8;
            cp16(sb + (unsigned)(2 * APLANE + plane * BPLANE + r * 80 + ch * 16), src);
        }
        asm volatile("cp.async.commit_group;");
    };

    float d[2][8][4];
    #pragma unroll
    for (int i = 0; i < 2; i++)
        #pragma unroll
        for (int j = 0; j < 8; j++)
            #pragma unroll
            for (int q = 0; q < 4; q++) d[i][j][q] = 0.f;

    copy_tile(0, 0);
    copy_tile(1, 1);

    for (int kt = 0; kt < 16; kt++) {
        if (kt < 15) asm volatile("cp.async.wait_group 1;" ::: "memory");
        else         asm volatile("cp.async.wait_group 0;" ::: "memory");
        __syncthreads();

        const unsigned sb = SB + (unsigned)(kt & 1) * STG_SZ;
        #pragma unroll
        for (int sub = 0; sub < 2; sub++) {
            const unsigned ko = (unsigned)(sub * 32);
            unsigned ah[2][4], al[2][4];
            #pragma unroll
            for (int i = 0; i < 2; i++) {
                unsigned ra = sb + (unsigned)((wm * 32 + i * 16 + rA) * 80) + ko + kA;
                ldsm4(ah[i], ra);
                ldsm4(al[i], ra + APLANE);
            }
            #pragma unroll
            for (int jp = 0; jp < 4; jp++) {
                unsigned bh4[4], bl4[4];
                unsigned rb = sb + 2 * APLANE
                            + (unsigned)((wn * 64 + jp * 16 + rB) * 80) + ko + kB;
                ldsm4(bh4, rb);
                ldsm4(bl4, rb + BPLANE);
                #pragma unroll
                for (int i = 0; i < 2; i++)
                    #pragma unroll
                    for (int jj = 0; jj < 2; jj++) {
                        float* dd = d[i][jp * 2 + jj];
                        mma_bf16(dd, ah[i], &bh4[jj * 2]);
                        mma_bf16(dd, ah[i], &bl4[jj * 2]);
                        mma_bf16(dd, al[i], &bh4[jj * 2]);
                    }
            }
        }
        __syncthreads();
        if (kt + 2 < 16) copy_tile(kt + 2, kt & 1);
    }

    #pragma unroll
    for (int j = 0; j < 8; j++) {
        int col = n0 + wn * 64 + j * 8 + t * 2;
        float b0 = bih[col] + bhh[col];
        float b1 = bih[col + 1] + bhh[col + 1];
        #pragma unroll
        for (int i = 0; i < 2; i++) {
            int row = m0 + wm * 32 + i * 16 + g;
            float2 v0; v0.x = d[i][j][0] + b0; v0.y = d[i][j][1] + b1;
            float2 v1; v1.x = d[i][j][2] + b0; v1.y = d[i][j][3] + b1;
            *(float2*)&g_xproj[(size_t)row * G4 + col] = v0;
            *(float2*)&g_xproj[(size_t)(row + 8) * G4 + col] = v1;
        }
    }
}

// =====================================================================================
// Kernel 2: persistent recurrence — EXACT R14 structure with ONE change: the post-poll
// block __syncthreads is replaced by per-half pollers (tid 0 / tid 256) + named
// barriers, so the two halves never converge block-wide between poll and MMA.
// Publish unchanged from R14: block sync + single red.release per block.
// =====================================================================================
#define SM_WH  0u
#define SM_WL  81920u
#define SM_HH  163840u
#define SM_HL  184320u
#define SM_RED 204800u
#define REC_SMEM (204800 + 4 * 1088 * 4)    // 222208

__global__ __launch_bounds__(512, 1)
void lstm_rec(const float* __restrict__ h0, const float* __restrict__ c0,
              float* __restrict__ out, int write_hc)
{
    extern __shared__ char sm[];
    const unsigned SB = smem_u32(sm);
    float* red = (float*)(sm + SM_RED);

    const int tid  = threadIdx.x;
    const int bi   = blockIdx.x >> 5;
    const int cj   = blockIdx.x & 31;
    const int lane = tid & 31;
    const int wid  = tid >> 5;
    const int nh   = wid & 3;
    const int kq   = wid >> 2;
    const int half = tid >> 8;              // 0: warps 0-7 (kq 0,1) / 1: warps 8-15

    const unsigned rA = (unsigned)(lane & 15);
    const unsigned kA = (unsigned)((lane >> 4) * 16);
    const unsigned rB = (unsigned)(((lane >> 4) << 3) | (lane & 7));
    const unsigned kB = (unsigned)(((lane >> 3) & 1) * 16);

    const int cb   = (tid & 255) >> 4;
    const int cjl  = tid & 15;
    const size_t hofs = (size_t)(bi * 16 + cb) * HID + cj * 16 + cjl;
    const int pp    = cj * 8 + (cjl >> 1);
    const int wslot = (pp >> 4) * 320 + cb * 20 + (pp & 15);

    int* cnt = &g_flags[0][bi];

    // ---- resident W_hh hi/lo ----
    for (int idx = tid; idx < 8192; idx += 512) {
        int plane = idx >> 12;
        int q = idx & 4095;
        int r = q >> 6, kt = (q >> 2) & 15, ch = q & 3;
        int ty = r >> 4, j = r & 15;
        const __nv_bfloat16* base = plane ? g_Rl : g_Rh;
        const __nv_bfloat16* src =
            base + (size_t)(ty * HID + cj * 16 + j) * HID + kt * 32 + ch * 8;
        cp16(SB + (plane ? SM_WL : SM_WH)
                + (unsigned)(kt * 5120 + r * 80 + ch * 16), src);
    }
    asm volatile("cp.async.commit_group;");

    // ---- init-publish h0 slice ----
    if (tid < 256) {
        float hv = h0[hofs];
        __nv_bfloat16 hb = __float2bfloat16(hv);
        unsigned hu = (unsigned)__bfloat16_as_ushort(hb);
        unsigned lu = (unsigned)__bfloat16_as_ushort(
                          __float2bfloat16(hv - __bfloat162float(hb)));
        unsigned hn2 = __shfl_down_sync(0xffffffffu, hu, 1);
        unsigned ln2 = __shfl_down_sync(0xffffffffu, lu, 1);
        if (!(cjl & 1)) {
            g_hbf[0][bi][0][wslot] = hu | (hn2 << 16);
            g_hbf[0][bi][1][wslot] = lu | (ln2 << 16);
        }
    }
    __syncthreads();
    if (tid == 0) red_rel_add(cnt, 1);

    asm volatile("cp.async.wait_group 0;" ::: "memory");
    float creg = (tid < 256) ? c0[hofs] : 0.0f;
    __syncthreads();

    for (int t = 0; t < SEQLEN; t++) {
        // ---- prefetch x_proj gates ----
        float xg0 = 0.f, xg1 = 0.f, xg2 = 0.f, xg3 = 0.f;
        if (tid < 256) {
            size_t xofs = ((size_t)t * BATCH + bi * 16 + cb) * G4 + cj * 16 + cjl;
            xg0 = __ldcg(&g_xproj[xofs]);
            xg1 = __ldcg(&g_xproj[xofs + HID]);
            xg2 = __ldcg(&g_xproj[xofs + 2 * HID]);
            xg3 = __ldcg(&g_xproj[xofs + 3 * HID]);
        }

        // ---- per-half poll of the shared per-bi counter (no block-wide sync) ----
        const int target = 32 * (t + 1);
        if (tid == 0)   { while (ld_acq(cnt) < target) { } }
        if (tid == 256) { while (ld_acq(cnt) < target) { } }
        if (half == 0) asm volatile("bar.sync 1, 256;" ::: "memory");
        else           asm volatile("bar.sync 2, 256;" ::: "memory");

        // ---- stage h_t: each 256-thread half stages ITS OWN kt slabs (20 KB) ----
        {
            const char* hsrc = (const char*)&g_hbf[t & 1][bi][0][0];
            const int tl = tid & 255;
            const unsigned hbase = (unsigned)(half * 10240);
            #pragma unroll
            for (int u = 0; u < 5; u++) {
                int idx = tl + u * 256;          // 0..1279
                int plane = idx >= 640;
                unsigned off = hbase + (unsigned)((idx - plane * 640) * 16);
                cp16(SB + (plane ? SM_HL : SM_HH) + off,
                     hsrc + plane * 20480 + off);
            }
            asm volatile("cp.async.commit_group;");
            asm volatile("cp.async.wait_group 0;" ::: "memory");
            if (half == 0) asm volatile("bar.sync 1, 256;" ::: "memory");
            else           asm volatile("bar.sync 2, 256;" ::: "memory");
        }

        // ---- HMMA: warp (nh, kq): 8 k16 chunks x 2 B-tiles x 3 split terms ----
        float d0[2][4] = {{0,0,0,0},{0,0,0,0}};
        float d1[2][4] = {{0,0,0,0},{0,0,0,0}};
        float d2[2][4] = {{0,0,0,0},{0,0,0,0}};
        #pragma unroll
        for (int c = 0; c < 8; c++) {
            int k16 = kq * 8 + c;
            unsigned hOff = (unsigned)((k16 >> 1) * 1280 + (k16 & 1) * 32);
            unsigned wOff = (unsigned)((k16 >> 1) * 5120 + (k16 & 1) * 32);
            unsigned ah4[4], al4[4], wh4[4], wl4[4];
            ldsm4(ah4, SB + SM_HH + hOff + rA * 80 + kA);
            ldsm4(al4, SB + SM_HL + hOff + rA * 80 + kA);
            ldsm4(wh4, SB + SM_WH + wOff + (unsigned)((nh * 16 + rB) * 80) + kB);
            ldsm4(wl4, SB + SM_WL + wOff + (unsigned)((nh * 16 + rB) * 80) + kB);
            #pragma unroll
            for (int jt = 0; jt < 2; jt++) {
                mma_bf16(d0[jt], ah4, &wh4[jt * 2]);
                mma_bf16(d1[jt], ah4, &wl4[jt * 2]);
                mma_bf16(d2[jt], al4, &wh4[jt * 2]);
            }
        }
        {
            const int g = lane >> 2, tq = lane & 3;
            #pragma unroll
            for (int jt = 0; jt < 2; jt++) {
                int n = nh * 16 + jt * 8 + tq * 2;
                int base = kq * 1088 + n * 17;
                red[base + g]          = d0[jt][0] + d1[jt][0] + d2[jt][0];
                red[base + 17 + g]     = d0[jt][1] + d1[jt][1] + d2[jt][1];
                red[base + g + 8]      = d0[jt][2] + d1[jt][2] + d2[jt][2];
                red[base + 17 + g + 8] = d0[jt][3] + d1[jt][3] + d2[jt][3];
            }
        }
        __syncthreads();

        // ---- phase C: reduce, gates, publish h_{t+1} (exact R14) ----
        float hn = 0.f;
        if (tid < 256) {
            float s[4];
            #pragma unroll
            for (int ty = 0; ty < 4; ty++) {
                int n = ty * 16 + cjl;
                float v = red[n * 17 + cb];
                #pragma unroll
                for (int kk = 1; kk < 4; kk++)
                    v += red[kk * 1088 + n * 17 + cb];
                s[ty] = v;
            }
            float iv = sigf(s[0] + xg0);
            float fv = sigf(s[1] + xg1);
            float gv = tanhf_acc(s[2] + xg2);
            float ov = sigf(s[3] + xg3);
            creg = fv * creg + iv * gv;
            hn = ov * tanhf_acc(creg);

            __nv_bfloat16 hb = __float2bfloat16(hn);
            unsigned hu = (unsigned)__bfloat16_as_ushort(hb);
            unsigned lu = (unsigned)__bfloat16_as_ushort(
                              __float2bfloat16(hn - __bfloat162float(hb)));
            unsigned hn2 = __shfl_down_sync(0xffffffffu, hu, 1);
            unsigned ln2 = __shfl_down_sync(0xffffffffu, lu, 1);
            if (!(cjl & 1)) {
                g_hbf[(t + 1) & 1][bi][0][wslot] = hu | (hn2 << 16);
                g_hbf[(t + 1) & 1][bi][1][wslot] = lu | (ln2 << 16);
            }
        }

        __syncthreads();
        if (tid == 0) red_rel_add(cnt, 1);

        // ---- out stores off the publish path ----
        if (tid < 256) {
            out[(size_t)t * (BATCH * HID) + hofs] = hn;
            if (write_hc && t == SEQLEN - 1) {
                out[(size_t)SEQLEN * BATCH * HID + hofs] = hn;
                out[(size_t)SEQLEN * BATCH * HID + BATCH * HID + hofs] = creg;
            }
        }
    }
}

// =====================================================================================
extern "C" void kernel_launch(void* const* d_in, const int* in_sizes, int n_in,
                              void* d_out, int out_size)
{
    const float* input = (const float*)d_in[0];
    const float* h0    = (const float*)d_in[1];
    const float* c0    = (const float*)d_in[2];
    const float* Wih   = (const float*)d_in[3];
    const float* Whh   = (const float*)d_in[4];
    const float* bih   = (const float*)d_in[5];
    const float* bhh   = (const float*)d_in[6];
    (void)in_sizes; (void)n_in;

    float* out = (float*)d_out;
    const int n_outputs = SEQLEN * BATCH * HID;
    int write_hc = (out_size >= n_outputs + 2 * BATCH * HID) ? 1 : 0;

    static int configured = 0;
    if (!configured) {
        cudaFuncSetAttribute(gemm_hmma, cudaFuncAttributeMaxDynamicSharedMemorySize,
                             GEMM_SMEM);
        cudaFuncSetAttribute(lstm_rec, cudaFuncAttributeMaxDynamicSharedMemorySize,
                             REC_SMEM);
        configured = 1;
    }

    __nv_bfloat16 *ah, *al, *wh, *wl, *rh, *rl;
    cudaGetSymbolAddress((void**)&ah, g_Ah);
    cudaGetSymbolAddress((void**)&al, g_Al);
    cudaGetSymbolAddress((void**)&wh, g_Wh);
    cudaGetSymbolAddress((void**)&wl, g_Wl);
    cudaGetSymbolAddress((void**)&rh, g_Rh);
    cudaGetSymbolAddress((void**)&rl, g_Rl);

    conv_split<<<512, 256>>>(Wih, wh, wl, (G4 * INP) / 4);
    conv_split<<<512, 256>>>(Whh, rh, rl, (G4 * HID) / 4);
    conv_split<<<2048, 256>>>(input, ah, al, (MTOT * INP) / 4);
    gemm_hmma<<<dim3(G4 / 128, MTOT / 128), 256, GEMM_SMEM>>>(bih, bhh);
    lstm_rec<<<NB_REC, 512, REC_SMEM>>>(h0, c0, out, write_hc);
}

// round 17
// speedup vs baseline: 1.0765x; 1.0132x over previous
#include <cuda_runtime.h>
#include <cuda_bf16.h>
#include <cstdint>
#include <cstddef>

#define SEQLEN 512
#define BATCH  64
#define HID    512
#define INP    512
#define G4     2048
#define NB_REC 128
#define MTOT   (SEQLEN * BATCH)

// ---------------- device scratch ----------------
__device__ float g_xproj[(size_t)SEQLEN * BATCH * G4];
__device__ int   g_flags[4][32];          // [bi][0..1] = per-(bi,half) publish counters
__device__ __align__(256) __nv_bfloat16 g_Ah[(size_t)MTOT * INP];
__device__ __align__(256) __nv_bfloat16 g_Al[(size_t)MTOT * INP];
__device__ __align__(256) __nv_bfloat16 g_Wh[(size_t)G4 * INP];
__device__ __align__(256) __nv_bfloat16 g_Wl[(size_t)G4 * INP];
__device__ __align__(256) __nv_bfloat16 g_Rh[(size_t)G4 * HID];
__device__ __align__(256) __nv_bfloat16 g_Rl[(size_t)G4 * HID];
// h exchange: DEPTH 4 (required by per-half counters; see skew-bound analysis)
__device__ __align__(256) unsigned g_hbf[4][4][2][5120];

// ---------------- helpers ----------------
__device__ __forceinline__ float sigf(float x) { return 1.0f / (1.0f + __expf(-x)); }
__device__ __forceinline__ float tanhf_acc(float x) {
    return 2.0f / (1.0f + __expf(-2.0f * x)) - 1.0f;
}
__device__ __forceinline__ unsigned smem_u32(const void* p) {
    unsigned a;
    asm("{ .reg .u64 t; cvta.to.shared.u64 t, %1; cvt.u32.u64 %0, t; }" : "=r"(a) : "l"(p));
    return a;
}
__device__ __forceinline__ void cp16(unsigned dst, const void* src) {
    asm volatile("cp.async.cg.shared.global [%0], [%1], 16;" :: "r"(dst), "l"(src));
}
__device__ __forceinline__ void ldsm4(unsigned* r, unsigned addr) {
    asm volatile("ldmatrix.sync.aligned.m8n8.x4.shared.b16 {%0,%1,%2,%3}, [%4];"
                 : "=r"(r[0]), "=r"(r[1]), "=r"(r[2]), "=r"(r[3]) : "r"(addr));
}
__device__ __forceinline__ void mma_bf16(float* d, const unsigned* a, const unsigned* b) {
    asm("mma.sync.aligned.m16n8k16.row.col.f32.bf16.bf16.f32 "
        "{%0,%1,%2,%3}, {%4,%5,%6,%7}, {%8,%9}, {%0,%1,%2,%3};"
        : "+f"(d[0]), "+f"(d[1]), "+f"(d[2]), "+f"(d[3])
        : "r"(a[0]), "r"(a[1]), "r"(a[2]), "r"(a[3]), "r"(b[0]), "r"(b[1]));
}
__device__ __forceinline__ int ld_acq(const int* p) {
    int v;
    asm volatile("ld.acquire.gpu.global.s32 %0, [%1];" : "=r"(v) : "l"(p) : "memory");
    return v;
}
__device__ __forceinline__ void red_rel_add(int* p, int v) {
    asm volatile("red.release.gpu.global.add.s32 [%0], %1;" :: "l"(p), "r"(v) : "memory");
}

// =====================================================================================
// fp32 -> bf16 hi/lo split. Block 0 also zeroes recurrence counters.
// =====================================================================================
__global__ void conv_split(const float* __restrict__ src, __nv_bfloat16* __restrict__ hi,
                           __nv_bfloat16* __restrict__ lo, int n4)
{
    if (blockIdx.x == 0 && threadIdx.x < 128) ((int*)g_flags)[threadIdx.x] = 0;
    int i = blockIdx.x * blockDim.x + threadIdx.x;
    int stride = gridDim.x * blockDim.x;
    for (; i < n4; i += stride) {
        float4 v = ((const float4*)src)[i];
        float f[4] = {v.x, v.y, v.z, v.w};
        unsigned hv0 = 0, hv1 = 0, lv0 = 0, lv1 = 0;
        #pragma unroll
        for (int j = 0; j < 4; j++) {
            __nv_bfloat16 h = __float2bfloat16(f[j]);
            __nv_bfloat16 l = __float2bfloat16(f[j] - __bfloat162float(h));
            unsigned hb = (unsigned)__bfloat16_as_ushort(h);
            unsigned lb = (unsigned)__bfloat16_as_ushort(l);
            if (j < 2) { hv0 |= hb << (16 * j);       lv0 |= lb << (16 * j); }
            else       { hv1 |= hb << (16 * (j - 2)); lv1 |= lb << (16 * (j - 2)); }
        }
        uint2 hh; hh.x = hv0; hh.y = hv1;
        uint2 ll; ll.x = lv0; ll.y = lv1;
        ((uint2*)hi)[i] = hh;
        ((uint2*)lo)[i] = ll;
    }
}

// =====================================================================================
// Kernel 1: xproj GEMM — EXACT round-13/14/16 version (128x128 tile, 2-stage, ldmatrix)
// =====================================================================================
#define KT 32
#define APLANE 10240
#define BPLANE 10240
#define STG_SZ (2 * APLANE + 2 * BPLANE)    // 40960
#define GEMM_SMEM (2 * STG_SZ)              // 81920

__global__ __launch_bounds__(256, 2)
void gemm_hmma(const float* __restrict__ bih, const float* __restrict__ bhh)
{
    extern __shared__ char smraw[];
    const unsigned SB = smem_u32(smraw);
    const int tid  = threadIdx.x;
    const int lane = tid & 31;
    const int wid  = tid >> 5;
    const int wm   = wid >> 1;
    const int wn   = wid & 1;
    const int g    = lane >> 2;
    const int t    = lane & 3;
    const int n0   = blockIdx.x * 128;
    const int m0   = blockIdx.y * 128;

    const unsigned rA = (unsigned)(lane & 15);
    const unsigned kA = (unsigned)((lane >> 4) * 16);
    const unsigned rB = (unsigned)(((lane >> 4) << 3) | (lane & 7));
    const unsigned kB = (unsigned)(((lane >> 3) & 1) * 16);

    auto copy_tile = [&](int kt, int sel) {
        const unsigned sb = SB + (unsigned)sel * STG_SZ;
        const int k0 = kt * KT;
        #pragma unroll
        for (int u = 0; u < 4; u++) {
            int idx = tid + u * 256;
            int plane = idx >> 9, r = (idx >> 2) & 127, ch = idx & 3;
            const __nv_bfloat16* src = (plane ? g_Al : g_Ah)
                                     + (size_t)(m0 + r) * INP + k0 + ch * 8;
            cp16(sb + (unsigned)(plane * APLANE + r * 80 + ch * 16), src);
        }
        #pragma unroll
        for (int u = 0; u < 4; u++) {
            int idx = tid + u * 256;
            int plane = idx >> 9, r = (idx >> 2) & 127, ch = idx & 3;
            const __nv_bfloat16* src = (plane ? g_Wl : g_Wh)
                                     + (size_t)(n0 + r) * INP + k0 + ch * 8;
            cp16(sb + (unsigned)(2 * APLANE + plane * BPLANE + r * 80 + ch * 16), src);
        }
        asm volatile("cp.async.commit_group;");
    };

    float d[2][8][4];
    #pragma unroll
    for (int i = 0; i < 2; i++)
        #pragma unroll
        for (int j = 0; j < 8; j++)
            #pragma unroll
            for (int q = 0; q < 4; q++) d[i][j][q] = 0.f;

    copy_tile(0, 0);
    copy_tile(1, 1);

    for (int kt = 0; kt < 16; kt++) {
        if (kt < 15) asm volatile("cp.async.wait_group 1;" ::: "memory");
        else         asm volatile("cp.async.wait_group 0;" ::: "memory");
        __syncthreads();

        const unsigned sb = SB + (unsigned)(kt & 1) * STG_SZ;
        #pragma unroll
        for (int sub = 0; sub < 2; sub++) {
            const unsigned ko = (unsigned)(sub * 32);
            unsigned ah[2][4], al[2][4];
            #pragma unroll
            for (int i = 0; i < 2; i++) {
                unsigned ra = sb + (unsigned)((wm * 32 + i * 16 + rA) * 80) + ko + kA;
                ldsm4(ah[i], ra);
                ldsm4(al[i], ra + APLANE);
            }
            #pragma unroll
            for (int jp = 0; jp < 4; jp++) {
                unsigned bh4[4], bl4[4];
                unsigned rb = sb + 2 * APLANE
                            + (unsigned)((wn * 64 + jp * 16 + rB) * 80) + ko + kB;
                ldsm4(bh4, rb);
                ldsm4(bl4, rb + BPLANE);
                #pragma unroll
                for (int i = 0; i < 2; i++)
                    #pragma unroll
                    for (int jj = 0; jj < 2; jj++) {
                        float* dd = d[i][jp * 2 + jj];
                        mma_bf16(dd, ah[i], &bh4[jj * 2]);
                        mma_bf16(dd, ah[i], &bl4[jj * 2]);
                        mma_bf16(dd, al[i], &bh4[jj * 2]);
                    }
            }
        }
        __syncthreads();
        if (kt + 2 < 16) copy_tile(kt + 2, kt & 1);
    }

    #pragma unroll
    for (int j = 0; j < 8; j++) {
        int col = n0 + wn * 64 + j * 8 + t * 2;
        float b0 = bih[col] + bhh[col];
        float b1 = bih[col + 1] + bhh[col + 1];
        #pragma unroll
        for (int i = 0; i < 2; i++) {
            int row = m0 + wm * 32 + i * 16 + g;
            float2 v0; v0.x = d[i][j][0] + b0; v0.y = d[i][j][1] + b1;
            float2 v1; v1.x = d[i][j][2] + b0; v1.y = d[i][j][3] + b1;
            *(float2*)&g_xproj[(size_t)row * G4 + col] = v0;
            *(float2*)&g_xproj[(size_t)(row + 8) * G4 + col] = v1;
        }
    }
}

// =====================================================================================
// Kernel 2: persistent recurrence — R16 with per-(bi,half) counters + depth-4 h buffer.
// Block cj publishes to cnt[bi][cj>>4] (one red.release by tid 0 per step).
// Consumer half h polls cnt[bi][h] (its 16 producers): target 16*(t+1).
// Depth-4 buffer guarantees reuse safety under the 1-step cross-half skew bound.
// =====================================================================================
#define SM_WH  0u
#define SM_WL  81920u
#define SM_HH  163840u
#define SM_HL  184320u
#define SM_RED 204800u
#define REC_SMEM (204800 + 4 * 1088 * 4)    // 222208

__global__ __launch_bounds__(512, 1)
void lstm_rec(const float* __restrict__ h0, const float* __restrict__ c0,
              float* __restrict__ out, int write_hc)
{
    extern __shared__ char sm[];
    const unsigned SB = smem_u32(sm);
    float* red = (float*)(sm + SM_RED);

    const int tid  = threadIdx.x;
    const int bi   = blockIdx.x >> 5;
    const int cj   = blockIdx.x & 31;
    const int lane = tid & 31;
    const int wid  = tid >> 5;
    const int nh   = wid & 3;
    const int kq   = wid >> 2;
    const int half = tid >> 8;              // consumer half

    const unsigned rA = (unsigned)(lane & 15);
    const unsigned kA = (unsigned)((lane >> 4) * 16);
    const unsigned rB = (unsigned)(((lane >> 4) << 3) | (lane & 7));
    const unsigned kB = (unsigned)(((lane >> 3) & 1) * 16);

    const int cb   = (tid & 255) >> 4;
    const int cjl  = tid & 15;
    const size_t hofs = (size_t)(bi * 16 + cb) * HID + cj * 16 + cjl;
    const int pp    = cj * 8 + (cjl >> 1);
    const int wslot = (pp >> 4) * 320 + cb * 20 + (pp & 15);

    int* cnt0 = &g_flags[bi][0];
    int* cnt1 = &g_flags[bi][1];
    int* cntp = &g_flags[bi][cj >> 4];      // counter this block publishes to

    // ---- resident W_hh hi/lo ----
    for (int idx = tid; idx < 8192; idx += 512) {
        int plane = idx >> 12;
        int q = idx & 4095;
        int r = q >> 6, kt = (q >> 2) & 15, ch = q & 3;
        int ty = r >> 4, j = r & 15;
        const __nv_bfloat16* base = plane ? g_Rl : g_Rh;
        const __nv_bfloat16* src =
            base + (size_t)(ty * HID + cj * 16 + j) * HID + kt * 32 + ch * 8;
        cp16(SB + (plane ? SM_WL : SM_WH)
                + (unsigned)(kt * 5120 + r * 80 + ch * 16), src);
    }
    asm volatile("cp.async.commit_group;");

    // ---- init-publish h0 slice into buf 0 ----
    if (tid < 256) {
        float hv = h0[hofs];
        __nv_bfloat16 hb = __float2bfloat16(hv);
        unsigned hu = (unsigned)__bfloat16_as_ushort(hb);
        unsigned lu = (unsigned)__bfloat16_as_ushort(
                          __float2bfloat16(hv - __bfloat162float(hb)));
        unsigned hn2 = __shfl_down_sync(0xffffffffu, hu, 1);
        unsigned ln2 = __shfl_down_sync(0xffffffffu, lu, 1);
        if (!(cjl & 1)) {
            g_hbf[0][bi][0][wslot] = hu | (hn2 << 16);
            g_hbf[0][bi][1][wslot] = lu | (ln2 << 16);
        }
    }
    __syncthreads();
    if (tid == 0) red_rel_add(cntp, 1);

    asm volatile("cp.async.wait_group 0;" ::: "memory");
    float creg = (tid < 256) ? c0[hofs] : 0.0f;
    __syncthreads();

    for (int t = 0; t < SEQLEN; t++) {
        // ---- prefetch x_proj gates ----
        float xg0 = 0.f, xg1 = 0.f, xg2 = 0.f, xg3 = 0.f;
        if (tid < 256) {
            size_t xofs = ((size_t)t * BATCH + bi * 16 + cb) * G4 + cj * 16 + cjl;
            xg0 = __ldcg(&g_xproj[xofs]);
            xg1 = __ldcg(&g_xproj[xofs + HID]);
            xg2 = __ldcg(&g_xproj[xofs + 2 * HID]);
            xg3 = __ldcg(&g_xproj[xofs + 3 * HID]);
        }

        // ---- per-half poll of ITS OWN counter (16 producers each) ----
        const int target = 16 * (t + 1);
        if (tid == 0)   { while (ld_acq(cnt0) < target) { } }
        if (tid == 256) { while (ld_acq(cnt1) < target) { } }
        if (half == 0) asm volatile("bar.sync 1, 256;" ::: "memory");
        else           asm volatile("bar.sync 2, 256;" ::: "memory");

        // ---- stage h_t from depth-4 buffer: each half stages ITS kt slabs ----
        {
            const char* hsrc = (const char*)&g_hbf[t & 3][bi][0][0];
            const int tl = tid & 255;
            const unsigned hbase = (unsigned)(half * 10240);
            #pragma unroll
            for (int u = 0; u < 5; u++) {
                int idx = tl + u * 256;          // 0..1279
                int plane = idx >= 640;
                unsigned off = hbase + (unsigned)((idx - plane * 640) * 16);
                cp16(SB + (plane ? SM_HL : SM_HH) + off,
                     hsrc + plane * 20480 + off);
            }
            asm volatile("cp.async.commit_group;");
            asm volatile("cp.async.wait_group 0;" ::: "memory");
            if (half == 0) asm volatile("bar.sync 1, 256;" ::: "memory");
            else           asm volatile("bar.sync 2, 256;" ::: "memory");
        }

        // ---- HMMA: warp (nh, kq): 8 k16 chunks x 2 B-tiles x 3 split terms ----
        float d0[2][4] = {{0,0,0,0},{0,0,0,0}};
        float d1[2][4] = {{0,0,0,0},{0,0,0,0}};
        float d2[2][4] = {{0,0,0,0},{0,0,0,0}};
        #pragma unroll
        for (int c = 0; c < 8; c++) {
            int k16 = kq * 8 + c;
            unsigned hOff = (unsigned)((k16 >> 1) * 1280 + (k16 & 1) * 32);
            unsigned wOff = (unsigned)((k16 >> 1) * 5120 + (k16 & 1) * 32);
            unsigned ah4[4], al4[4], wh4[4], wl4[4];
            ldsm4(ah4, SB + SM_HH + hOff + rA * 80 + kA);
            ldsm4(al4, SB + SM_HL + hOff + rA * 80 + kA);
            ldsm4(wh4, SB + SM_WH + wOff + (unsigned)((nh * 16 + rB) * 80) + kB);
            ldsm4(wl4, SB + SM_WL + wOff + (unsigned)((nh * 16 + rB) * 80) + kB);
            #pragma unroll
            for (int jt = 0; jt < 2; jt++) {
                mma_bf16(d0[jt], ah4, &wh4[jt * 2]);
                mma_bf16(d1[jt], ah4, &wl4[jt * 2]);
                mma_bf16(d2[jt], al4, &wh4[jt * 2]);
            }
        }
        {
            const int g = lane >> 2, tq = lane & 3;
            #pragma unroll
            for (int jt = 0; jt < 2; jt++) {
                int n = nh * 16 + jt * 8 + tq * 2;
                int base = kq * 1088 + n * 17;
                red[base + g]          = d0[jt][0] + d1[jt][0] + d2[jt][0];
                red[base + 17 + g]     = d0[jt][1] + d1[jt][1] + d2[jt][1];
                red[base + g + 8]      = d0[jt][2] + d1[jt][2] + d2[jt][2];
                red[base + 17 + g + 8] = d0[jt][3] + d1[jt][3] + d2[jt][3];
            }
        }
        __syncthreads();

        // ---- phase C: reduce, gates, publish h_{t+1} into buf (t+1)&3 ----
        float hn = 0.f;
        if (tid < 256) {
            float s[4];
            #pragma unroll
            for (int ty = 0; ty < 4; ty++) {
                int n = ty * 16 + cjl;
                float v = red[n * 17 + cb];
                #pragma unroll
                for (int kk = 1; kk < 4; kk++)
                    v += red[kk * 1088 + n * 17 + cb];
                s[ty] = v;
            }
            float iv = sigf(s[0] + xg0);
            float fv = sigf(s[1] + xg1);
            float gv = tanhf_acc(s[2] + xg2);
            float ov = sigf(s[3] + xg3);
            creg = fv * creg + iv * gv;
            hn = ov * tanhf_acc(creg);

            __nv_bfloat16 hb = __float2bfloat16(hn);
            unsigned hu = (unsigned)__bfloat16_as_ushort(hb);
            unsigned lu = (unsigned)__bfloat16_as_ushort(
                              __float2bfloat16(hn - __bfloat162float(hb)));
            unsigned hn2 = __shfl_down_sync(0xffffffffu, hu, 1);
            unsigned ln2 = __shfl_down_sync(0xffffffffu, lu, 1);
            if (!(cjl & 1)) {
                g_hbf[(t + 1) & 3][bi][0][wslot] = hu | (hn2 << 16);
                g_hbf[(t + 1) & 3][bi][1][wslot] = lu | (ln2 << 16);
            }
        }

        __syncthreads();
        if (tid == 0) red_rel_add(cntp, 1);

        // ---- out stores off the publish path ----
        if (tid < 256) {
            out[(size_t)t * (BATCH * HID) + hofs] = hn;
            if (write_hc && t == SEQLEN - 1) {
                out[(size_t)SEQLEN * BATCH * HID + hofs] = hn;
                out[(size_t)SEQLEN * BATCH * HID + BATCH * HID + hofs] = creg;
            }
        }
    }
}

// =====================================================================================
extern "C" void kernel_launch(void* const* d_in, const int* in_sizes, int n_in,
                              void* d_out, int out_size)
{
    const float* input = (const float*)d_in[0];
    const float* h0    = (const float*)d_in[1];
    const float* c0    = (const float*)d_in[2];
    const float* Wih   = (const float*)d_in[3];
    const float* Whh   = (const float*)d_in[4];
    const float* bih   = (const float*)d_in[5];
    const float* bhh   = (const float*)d_in[6];
    (void)in_sizes; (void)n_in;

    float* out = (float*)d_out;
    const int n_outputs = SEQLEN * BATCH * HID;
    int write_hc = (out_size >= n_outputs + 2 * BATCH * HID) ? 1 : 0;

    static int configured = 0;
    if (!configured) {
        cudaFuncSetAttribute(gemm_hmma, cudaFuncAttributeMaxDynamicSharedMemorySize,
                             GEMM_SMEM);
        cudaFuncSetAttribute(lstm_rec, cudaFuncAttributeMaxDynamicSharedMemorySize,
                             REC_SMEM);
        configured = 1;
    }

    __nv_bfloat16 *ah, *al, *wh, *wl, *rh, *rl;
    cudaGetSymbolAddress((void**)&ah, g_Ah);
    cudaGetSymbolAddress((void**)&al, g_Al);
    cudaGetSymbolAddress((void**)&wh, g_Wh);
    cudaGetSymbolAddress((void**)&wl, g_Wl);
    cudaGetSymbolAddress((void**)&rh, g_Rh);
    cudaGetSymbolAddress((void**)&rl, g_Rl);

    conv_split<<<512, 256>>>(Wih, wh, wl, (G4 * INP) / 4);
    conv_split<<<512, 256>>>(Whh, rh, rl, (G4 * HID) / 4);
    conv_split<<<2048, 256>>>(input, ah, al, (MTOT * INP) / 4);
    gemm_hmma<<<dim3(G4 / 128, MTOT / 128), 256, GEMM_SMEM>>>(bih, bhh);
    lstm_rec<<<NB_REC, 512, REC_SMEM>>>(h0, c0, out, write_hc);
}